// round 12
// baseline (speedup 1.0000x reference)
#include <cuda_runtime.h>
#include <cuda_fp16.h>
#include <cstdint>

#define BATCH 8
#define HH    128
#define WW    128
#define CIN   256
#define COUT  256
#define KTOT  2304           // 9 * CIN
#define NKC   36             // 2304 / 64
#define STAGES 3
#define STAGE_BYTES 32768    // A 16K + B 16K
#define SMEM_BYTES (STAGES * STAGE_BYTES)

// ---------------- static device scratch ----------------
__device__ float g_demod[BATCH * COUT];
__device__ float g_k2t[COUT * CIN];                          // sum_tap w^2, [co][ci]
__device__ __align__(16) __half g_xh[BATCH * HH * WW * CIN]; // x*style (fp16)
__device__ __align__(16) __half g_wh[KTOT * COUT];           // weights fp16 [k][n]

// ---------------- PTX helpers (all plain sm_80-class) ----------------
static __device__ __forceinline__ uint32_t s2u(const void* p) {
    uint32_t a;
    asm("{ .reg .u64 t; cvta.to.shared.u64 t, %1; cvt.u32.u64 %0, t; }"
        : "=r"(a) : "l"(p));
    return a;
}
static __device__ __forceinline__ void cpasync(uint32_t dst, const void* src,
                                               uint32_t srcsz) {
    asm volatile("cp.async.cg.shared.global [%0], [%1], 16, %2;"
                 :: "r"(dst), "l"(src), "r"(srcsz) : "memory");
}
#define CP_COMMIT() asm volatile("cp.async.commit_group;" ::: "memory")
#define CP_WAIT1()  asm volatile("cp.async.wait_group 1;" ::: "memory")

static __device__ __forceinline__ void ldsm4(uint32_t* r, uint32_t a) {
    asm volatile("ldmatrix.sync.aligned.m8n8.x4.shared.b16 {%0,%1,%2,%3}, [%4];"
                 : "=r"(r[0]), "=r"(r[1]), "=r"(r[2]), "=r"(r[3]) : "r"(a));
}
static __device__ __forceinline__ void ldsm4t(uint32_t* r, uint32_t a) {
    asm volatile("ldmatrix.sync.aligned.m8n8.x4.trans.shared.b16 {%0,%1,%2,%3}, [%4];"
                 : "=r"(r[0]), "=r"(r[1]), "=r"(r[2]), "=r"(r[3]) : "r"(a));
}
static __device__ __forceinline__ void mma16816(float* c, const uint32_t* a,
                                                uint32_t b0, uint32_t b1) {
    asm volatile(
        "mma.sync.aligned.m16n8k16.row.col.f32.f16.f16.f32 "
        "{%0,%1,%2,%3}, {%4,%5,%6,%7}, {%8,%9}, {%0,%1,%2,%3};"
        : "+f"(c[0]), "+f"(c[1]), "+f"(c[2]), "+f"(c[3])
        : "r"(a[0]), "r"(a[1]), "r"(a[2]), "r"(a[3]), "r"(b0), "r"(b1));
}

// ---------------- pre-pass kernels ----------------
// Fused weight pass: fp16 convert + tap-reduction of squares (one read of kern)
__global__ void w_pre_kernel(const float* __restrict__ kern) {
    int ci = blockIdx.x;
    int co = threadIdx.x;
    float s = 0.0f;
    #pragma unroll
    for (int tap = 0; tap < 9; ++tap) {
        size_t idx = (size_t)(tap * CIN + ci) * COUT + co;
        float w = kern[idx];
        g_wh[idx] = __float2half_rn(w);
        s = fmaf(w, w, s);
    }
    g_k2t[co * CIN + ci] = s;
}

__global__ __launch_bounds__(256) void demod_kernel(const float* __restrict__ style) {
    int gw   = blockIdx.x * 8 + (threadIdx.x >> 5);   // 0..2047
    int lane = threadIdx.x & 31;
    int b  = gw >> 8;
    int co = gw & 255;
    float acc = 0.0f;
    #pragma unroll
    for (int t = 0; t < 8; ++t) {
        int ci = t * 32 + lane;
        float s = style[b * CIN + ci];
        acc = fmaf(s * s, g_k2t[co * CIN + ci], acc);
    }
    #pragma unroll
    for (int o = 16; o > 0; o >>= 1)
        acc += __shfl_xor_sync(0xFFFFFFFF, acc, o);
    if (lane == 0) g_demod[b * COUT + co] = rsqrtf(acc + 1e-7f);
}

__global__ __launch_bounds__(256) void mod_x_kernel(
    const float* __restrict__ x, const float* __restrict__ style) {
    size_t e = ((size_t)blockIdx.x * 256 + threadIdx.x) * 4;
    int ci = (int)(e & 255);
    int b  = (int)(e >> 22);
    float4 xv = *(const float4*)(x + e);
    float4 sv = *(const float4*)(style + b * CIN + ci);
    __half2 p01 = __floats2half2_rn(xv.x * sv.x, xv.y * sv.y);
    __half2 p23 = __floats2half2_rn(xv.z * sv.z, xv.w * sv.w);
    *(uint2*)(g_xh + e) = make_uint2(*(uint32_t*)&p01, *(uint32_t*)&p23);
}

// ---------------- main mma.sync kernel ----------------
// CTA tile 128(M) x 128(N) x 64(K). 8 warps: wm in {0,1}, wn in {0..3}.
// Single-product fp16: acc += A*B.
// Stage: A @0 (16K: 128 rows x 128B), B @16K (16K: 64 rows x 256B). 3 stages.
// A swizzle: 8 chunks/row: chunk' = c ^ (row&7)
// B swizzle: 16 chunks/row: chunk' = c ^ (krow&7)
// One __syncthreads per 64-wide K iteration (36 total).
__global__ __launch_bounds__(256, 2) void conv_mma_kernel(float* __restrict__ out) {
    extern __shared__ char dsm[];
    const uint32_t smem = s2u(dsm);
    const int tid  = threadIdx.x;
    const int wid  = tid >> 5;
    const int lane = tid & 31;
    const int wm = wid & 1;
    const int wn = wid >> 1;
    const int mt = blockIdx.x;       // 128 consecutive m = one image row
    const int n0 = blockIdx.y * 128;
    const int b  = mt >> 7;
    const int h  = mt & 127;
    const int m0 = mt * 128;

    // loader constants
    const int arow = tid >> 1;          // 0..127 = w pixel
    const int ac0  = (tid & 1) * 4;     // A chunk base (4 chunks of 16B)
    const int brow = tid >> 2;          // 0..63 = k row
    const int bc0  = (tid & 3) * 4;     // B chunk base (4 chunks of 16B)

    auto load_stage = [&](int kc, int stage) {
        const uint32_t sb = smem + (uint32_t)stage * STAGE_BYTES;
        const int tap = kc >> 2;            // 64 | 256: slice within one tap
        const int ci0 = (kc & 3) << 6;
        const int dh  = tap / 3;
        const int dw  = tap - dh * 3;
        const int ih  = h + dh - 1;
        const int iw  = arow + dw - 1;
        const bool v  = ((unsigned)ih < HH) && ((unsigned)iw < WW);
        const uint32_t sz = v ? 16u : 0u;
        const size_t gA = (((size_t)b * HH + (v ? ih : 0)) * WW + (v ? iw : 0)) * CIN + ci0;
        const uint32_t da = sb + (uint32_t)arow * 128u;
        #pragma unroll
        for (int j = 0; j < 4; ++j) {
            int c = ac0 + j;
            uint32_t off = (uint32_t)((c ^ (arow & 7)) * 16);
            cpasync(da + off, g_xh + gA + c * 8, sz);
        }
        const size_t gB = (size_t)(kc * 64 + brow) * COUT + n0;
        const uint32_t db = sb + 16384u + (uint32_t)brow * 256u;
        #pragma unroll
        for (int j = 0; j < 4; ++j) {
            int c = bc0 + j;
            uint32_t off = (uint32_t)((c ^ (brow & 7)) * 16);
            cpasync(db + off, g_wh + gB + c * 8, 16u);
        }
    };

    // ldmatrix lane constants
    const int lr = lane & 7;
    const int lg = lane >> 3;
    const int cg = lg >> 1;
    int rowA[4];
    #pragma unroll
    for (int mb = 0; mb < 4; ++mb)
        rowA[mb] = wm * 64 + mb * 16 + lr + (lg & 1) * 8;
    const int rkb = (lg & 1) * 8 + lr;

    float acc[4][4][4];
    #pragma unroll
    for (int mb = 0; mb < 4; ++mb)
        #pragma unroll
        for (int nb = 0; nb < 4; ++nb)
            #pragma unroll
            for (int q = 0; q < 4; ++q) acc[mb][nb][q] = 0.0f;

    load_stage(0, 0); CP_COMMIT();
    load_stage(1, 1); CP_COMMIT();

    int st = 0;
    for (int kc = 0; kc < NKC; ++kc) {
        CP_WAIT1();
        __syncthreads();
        const int nk = kc + 2;
        const int sl = (st + 2 >= STAGES) ? st - 1 : st + 2;
        if (nk < NKC) load_stage(nk, sl);
        CP_COMMIT();

        const uint32_t sb = smem + (uint32_t)st * STAGE_BYTES;
        #pragma unroll
        for (int ks = 0; ks < 4; ++ks) {             // 4 x K=16 within tile
            uint32_t a[4][4], bh[2][4];
            #pragma unroll
            for (int mb = 0; mb < 4; ++mb) {
                int ch = 2 * ks + cg;                // 0..7
                ldsm4(a[mb], sb + (uint32_t)(rowA[mb] * 128 +
                             ((ch ^ (rowA[mb] & 7)) * 16)));
            }
            #pragma unroll
            for (int h2 = 0; h2 < 2; ++h2) {
                int rk = ks * 16 + rkb;              // 0..63
                int ch = wn * 4 + h2 * 2 + cg;       // 0..15
                ldsm4t(bh[h2], sb + 16384u + (uint32_t)(rk * 256 +
                               ((ch ^ (rk & 7)) * 16)));
            }
            #pragma unroll
            for (int mb = 0; mb < 4; ++mb)
                #pragma unroll
                for (int nb = 0; nb < 4; ++nb)
                    mma16816(acc[mb][nb], a[mb],
                             bh[nb >> 1][2 * (nb & 1)], bh[nb >> 1][2 * (nb & 1) + 1]);
        }
        st = (st + 1 == STAGES) ? 0 : st + 1;
    }

    // ---- epilogue: demod + store ----
    const int mbase = m0 + wm * 64;
    const int nbase = n0 + wn * 32;
    const float* dmp = g_demod + b * COUT;
    float dm[4][2];
    #pragma unroll
    for (int nb = 0; nb < 4; ++nb) {
        int n = nbase + nb * 8 + (lane & 3) * 2;
        dm[nb][0] = __ldg(dmp + n);
        dm[nb][1] = __ldg(dmp + n + 1);
    }
    #pragma unroll
    for (int mb = 0; mb < 4; ++mb) {
        #pragma unroll
        for (int r2 = 0; r2 < 2; ++r2) {
            int m = mbase + mb * 16 + (lane >> 2) + r2 * 8;
            float* op = out + (size_t)m * COUT;
            #pragma unroll
            for (int nb = 0; nb < 4; ++nb) {
                int n = nbase + nb * 8 + (lane & 3) * 2;
                float2 v;
                v.x = acc[mb][nb][2 * r2]     * dm[nb][0];
                v.y = acc[mb][nb][2 * r2 + 1] * dm[nb][1];
                *(float2*)(op + n) = v;
            }
        }
    }
}

// ---------------- host launch ----------------
extern "C" void kernel_launch(void* const* d_in, const int* in_sizes, int n_in,
                              void* d_out, int out_size) {
    const float* x     = (const float*)d_in[0];   // (8,128,128,256)
    const float* style = (const float*)d_in[1];   // (8,256)
    const float* kern  = (const float*)d_in[2];   // (3,3,256,256)
    float* out = (float*)d_out;

    w_pre_kernel<<<CIN, COUT>>>(kern);
    mod_x_kernel<<<(BATCH * HH * WW * CIN) / 4 / 256, 256>>>(x, style);
    demod_kernel<<<256, 256>>>(style);

    cudaFuncSetAttribute(conv_mma_kernel,
                         cudaFuncAttributeMaxDynamicSharedMemorySize, SMEM_BYTES);
    dim3 grid(1024, 2);
    conv_mma_kernel<<<grid, 256, SMEM_BYTES>>>(out);
}